// round 5
// baseline (speedup 1.0000x reference)
#include <cuda_runtime.h>
#include <math.h>
#include <stdint.h>

#define Nn 8192
#define Ee 131072
#define Hh 128
#define NEGV (-1e30f)
#define NSLAB 16
#define PAD_A 68
#define PAD_B 132
#define SMEM_BYTES ((128*PAD_A + 128*PAD_B)*4)   // 100 KB -> 2 CTAs/SM

// ---------------- device scratch (no allocations allowed) ----------------
__device__ __align__(16) float g_deg[Nn];
__device__ __align__(16) float g_rsq[Nn];
__device__ __align__(16) float g_xw[Nn*Hh];
__device__ __align__(16) float g_agg[Nn*Hh];
__device__ __align__(16) float g_h[Nn*Hh];
__device__ __align__(16) float g_t[Nn*Hh];
__device__ __align__(16) float g_Ht[Nn*Hh];
__device__ __align__(16) float g_Hs[Nn*Hh];
__device__ __align__(16) float g_P[Nn*Hh];
__device__ __align__(16) float g_Q[Nn*Hh];
__device__ __align__(16) float g_vz[Hh];
__device__ __align__(16) float g_czb[Hh];
__device__ int   g_cv[Nn];
__device__ __align__(16) float g_pval[Nn*NSLAB*2];
__device__ int   g_pidx[Nn*NSLAB*2];

#define SEL_H  0
#define SEL_XW 1
#define SEL_T  2
__device__ __forceinline__ float* buf_ptr(int sel) {
    switch (sel) {
        case SEL_H:  return g_h;
        case SEL_XW: return g_xw;
        default:     return g_t;
    }
}

// ---------------- packed f32x2 helpers ----------------
__device__ __forceinline__ unsigned long long pack2(float x, float y) {
    unsigned long long r;
    asm("mov.b64 %0, {%1, %2};" : "=l"(r) : "f"(x), "f"(y));
    return r;
}
__device__ __forceinline__ float2 unpack2(unsigned long long v) {
    float2 r;
    asm("mov.b64 {%0, %1}, %2;" : "=f"(r.x), "=f"(r.y) : "l"(v));
    return r;
}
__device__ __forceinline__ void fma2(unsigned long long &acc, unsigned long long a2, unsigned long long b2) {
    asm("fma.rn.f32x2 %0, %1, %2, %0;" : "+l"(acc) : "l"(a2), "l"(b2));
}
__device__ __forceinline__ void red4(float* p, float a, float b, float c, float d) {
    asm volatile("red.global.add.v4.f32 [%0], {%1,%2,%3,%4};"
                 :: "l"(p), "f"(a), "f"(b), "f"(c), "f"(d) : "memory");
}

// k-major transpose load, 64 rows: G[row0..row0+64) x 128 (stride ld) -> S[k][r], r<64
__device__ __forceinline__ void load_tile_T64(const float* __restrict__ G, int row0, int ld,
                                              float* S, int tid) {
#pragma unroll
    for (int i = 0; i < 8; i++) {
        int r  = (tid & 31) + 32*(i >> 2);
        int kq = (tid >> 5) + 8*(i & 3);
        float4 v = *(const float4*)(G + (row0 + r)*ld + kq*4);
        S[(kq*4+0)*PAD_A + r] = v.x;
        S[(kq*4+1)*PAD_A + r] = v.y;
        S[(kq*4+2)*PAD_A + r] = v.z;
        S[(kq*4+3)*PAD_A + r] = v.w;
    }
}
// k-major transpose load, 128 rows -> S[k][r], r<128 (row stride PAD_B)
__device__ __forceinline__ void load_tile_T128(const float* __restrict__ G, int row0, int ld,
                                               float* S, int tid) {
#pragma unroll
    for (int i = 0; i < 16; i++) {
        int r  = (tid & 31) + 32*(i >> 2);
        int kq = (tid >> 5) + 8*(i & 3);
        float4 v = *(const float4*)(G + (row0 + r)*ld + kq*4);
        S[(kq*4+0)*PAD_B + r] = v.x;
        S[(kq*4+1)*PAD_B + r] = v.y;
        S[(kq*4+2)*PAD_B + r] = v.z;
        S[(kq*4+3)*PAD_B + r] = v.w;
    }
}

// 4x8 microtile over K=128: As 64-row tile, Bs 128-row tile, f32x2 accumulators [4][4]
__device__ __forceinline__ void mm48(const float* As, const float* Bs, int ty, int tx,
                                     unsigned long long accp[4][4]) {
#pragma unroll 4
    for (int k = 0; k < 128; k++) {
        const float4 a  = *(const float4*)&As[k*PAD_A + ty*4];
        const float4 b0 = *(const float4*)&Bs[k*PAD_B + tx*8];
        const float4 b1 = *(const float4*)&Bs[k*PAD_B + tx*8 + 4];
        unsigned long long bp[4];
        bp[0] = pack2(b0.x, b0.y); bp[1] = pack2(b0.z, b0.w);
        bp[2] = pack2(b1.x, b1.y); bp[3] = pack2(b1.z, b1.w);
        float av[4] = {a.x, a.y, a.z, a.w};
#pragma unroll
        for (int i = 0; i < 4; i++) {
            unsigned long long ap = pack2(av[i], av[i]);
            fma2(accp[i][0], ap, bp[0]);
            fma2(accp[i][1], ap, bp[1]);
            fma2(accp[i][2], ap, bp[2]);
            fma2(accp[i][3], ap, bp[3]);
        }
    }
}

// ---------------- small kernels ----------------
__global__ void k_deg_init() {
    int i = blockIdx.x*blockDim.x + threadIdx.x;
    if (i < Nn) g_deg[i] = 1.0f;
}
__global__ void k_deg_count(const int* __restrict__ dst) {
    int e = blockIdx.x*blockDim.x + threadIdx.x;
    if (e < Ee) atomicAdd(&g_deg[dst[e]], 1.0f);
}
__global__ void k_rsq() {
    int i = blockIdx.x*blockDim.x + threadIdx.x;
    if (i < Nn) g_rsq[i] = rsqrtf(g_deg[i]);
}
__global__ void k_xw1(const float* __restrict__ x, const float* __restrict__ w) {
    int idx = blockIdx.x*blockDim.x + threadIdx.x;
    if (idx >= Nn*Hh) return;
    int i = idx >> 7, j = idx & 127;
    g_xw[idx] = fmaf(x[2*i], w[2*j], x[2*i+1]*w[2*j+1]);
    g_agg[idx] = 0.0f;
}
__global__ void k_edge_agg(const int* __restrict__ src, const int* __restrict__ dst) {
    int idx = blockIdx.x*blockDim.x + threadIdx.x;
    if (idx >= Ee*32) return;
    int e = idx >> 5, q = idx & 31;
    int s = src[e], d = dst[e];
    float sc = g_rsq[s]*g_rsq[d];
    const float4 v = *(const float4*)(g_xw + s*Hh + q*4);
    red4(g_agg + d*Hh + q*4, sc*v.x, sc*v.y, sc*v.z, sc*v.w);
}
__global__ void k_post(const float* __restrict__ b) {
    int idx = blockIdx.x*blockDim.x + threadIdx.x;
    if (idx >= Nn*Hh) return;
    int i = idx >> 7, j = idx & 127;
    float v = g_agg[idx] + g_xw[idx]/g_deg[i] + b[j];
    g_h[idx] = fmaxf(v, 0.0f);
}
__global__ void k_zvec(const float* __restrict__ np1w, const float* __restrict__ np1b,
                       const float* __restrict__ i1w, const float* __restrict__ i1b,
                       const float* __restrict__ z) {
    int t = threadIdx.x;
    if (t < 128) {
        float s = np1b[t];
        for (int k = 0; k < 128; k++) s = fmaf(np1w[t*256 + 128 + k], z[k], s);
        g_vz[t] = s;
    } else if (t < 256) {
        int j = t - 128;
        float s = i1b[j];
        for (int k = 0; k < 128; k++) s = fmaf(i1w[j*384 + 256 + k], z[k], s);
        g_czb[j] = s;
    }
}
__global__ void k_cv(const int* __restrict__ depth) {
    int v = blockIdx.x*blockDim.x + threadIdx.x;
    if (v >= Nn) return;
    int thr = depth[v] + 1;
    int lo = 0, hi = Nn;
    while (lo < hi) { int mid = (lo + hi) >> 1; if (depth[mid] <= thr) lo = mid + 1; else hi = mid; }
    g_cv[v] = lo;
#pragma unroll
    for (int s = 0; s < NSLAB*2; s++) {
        g_pval[v*NSLAB*2 + s] = -INFINITY;
        g_pidx[v*NSLAB*2 + s] = 0x7fffffff;
    }
}

// ---------------- fp32 GEMM: C[8192 x 128] = A @ W^T (+bias, relu), 64-row tiles ----------------
__global__ void __launch_bounds__(256) k_gemm(
    int a_sel, const float* __restrict__ W, int ldw,
    const float* __restrict__ bias, int bias_vz, int c_sel, int relu, int zero_agg)
{
    extern __shared__ float sm[];
    float* As = sm;
    float* Bs = sm + 128*PAD_A;
    const float* A = buf_ptr(a_sel);
    float* C = buf_ptr(c_sel);
    const float* bptr = bias_vz ? g_vz : bias;
    int tid = threadIdx.x;
    int r0 = blockIdx.x * 64;

    load_tile_T64(A, r0, 128, As, tid);
    load_tile_T128(W, 0, ldw, Bs, tid);
    __syncthreads();

    int ty = tid >> 4, tx = tid & 15;
    unsigned long long accp[4][4];
#pragma unroll
    for (int i = 0; i < 4; i++)
#pragma unroll
        for (int j = 0; j < 4; j++) accp[i][j] = 0ull;
    mm48(As, Bs, ty, tx, accp);

#pragma unroll
    for (int i = 0; i < 4; i++) {
        int r = r0 + ty*4 + i;
        float o[8];
#pragma unroll
        for (int jp = 0; jp < 4; jp++) {
            float2 f = unpack2(accp[i][jp]);
            o[2*jp] = f.x; o[2*jp+1] = f.y;
        }
#pragma unroll
        for (int j = 0; j < 8; j++) {
            if (bptr) o[j] += bptr[tx*8 + j];
            if (relu) o[j] = fmaxf(o[j], 0.0f);
        }
        *(float4*)(C + r*128 + tx*8)     = make_float4(o[0], o[1], o[2], o[3]);
        *(float4*)(C + r*128 + tx*8 + 4) = make_float4(o[4], o[5], o[6], o[7]);
        if (zero_agg) {
            *(float4*)(g_agg + r*128 + tx*8)     = make_float4(0.f, 0.f, 0.f, 0.f);
            *(float4*)(g_agg + r*128 + tx*8 + 4) = make_float4(0.f, 0.f, 0.f, 0.f);
        }
    }
}

// fused 4-way projection: blockIdx.y selects (W, ld, C): Ht, Hs, P, Q
__global__ void __launch_bounds__(256) k_proj(
    const float* __restrict__ tgtw, const float* __restrict__ srcw,
    const float* __restrict__ i1w)
{
    extern __shared__ float sm[];
    float* As = sm;
    float* Bs = sm + 128*PAD_A;
    const float* W; int ldw; float* C;
    switch (blockIdx.y) {
        case 0: W = tgtw;       ldw = 128; C = g_Ht; break;
        case 1: W = srcw;       ldw = 128; C = g_Hs; break;
        case 2: W = i1w;        ldw = 384; C = g_P;  break;
        default: W = i1w + 128; ldw = 384; C = g_Q;  break;
    }
    int tid = threadIdx.x;
    int r0 = blockIdx.x * 64;

    load_tile_T64(g_h, r0, 128, As, tid);
    load_tile_T128(W, 0, ldw, Bs, tid);
    __syncthreads();

    int ty = tid >> 4, tx = tid & 15;
    unsigned long long accp[4][4];
#pragma unroll
    for (int i = 0; i < 4; i++)
#pragma unroll
        for (int j = 0; j < 4; j++) accp[i][j] = 0ull;
    mm48(As, Bs, ty, tx, accp);

#pragma unroll
    for (int i = 0; i < 4; i++) {
        int r = r0 + ty*4 + i;
#pragma unroll
        for (int jp = 0; jp < 2; jp++) {
            float2 f0 = unpack2(accp[i][2*jp]);
            float2 f1 = unpack2(accp[i][2*jp+1]);
            *(float4*)(C + r*128 + tx*8 + 4*jp) = make_float4(f0.x, f0.y, f1.x, f1.y);
        }
    }
}

// ---------------- fused score GEMM + masked top-2 ----------------
// grid (NSLAB, Nn/64). slab s handles chunks c ≡ s (mod NSLAB); chunk c = u in [c*128, c*128+128).
__global__ void __launch_bounds__(256) k_score()
{
    extern __shared__ float sm[];
    float* As = sm;
    float* Bs = sm + 128*PAD_A;
    int v0 = blockIdx.y * 64;
    int slab = blockIdx.x;

    int cmax = g_cv[v0 + 63];           // c_v non-decreasing (depth sorted)
    int uend = cmax < 2 ? 2 : cmax;     // >=2 so masked NEG idx ties match top_k
    if (uend > Nn) uend = Nn;
    int nchunk = (uend + 127) >> 7;
    if (slab >= nchunk) return;

    int tid = threadIdx.x;
    load_tile_T64(g_Ht, v0, 128, As, tid);

    int ty = tid >> 4, tx = tid & 15;
    int cvr[4]; float b1[4], b2[4]; int i1[4], i2[4];
#pragma unroll
    for (int i = 0; i < 4; i++) {
        cvr[i] = g_cv[v0 + ty*4 + i];
        b1[i] = -INFINITY; b2[i] = -INFINITY; i1[i] = 0x7fffffff; i2[i] = 0x7fffffff;
    }

    for (int c = slab; c < nchunk; c += NSLAB) {
        __syncthreads();
        load_tile_T128(g_Hs, c*128, 128, Bs, tid);
        __syncthreads();

        unsigned long long accp[4][4];
#pragma unroll
        for (int i = 0; i < 4; i++)
#pragma unroll
            for (int j = 0; j < 4; j++) accp[i][j] = 0ull;
        mm48(As, Bs, ty, tx, accp);

        int ub = c*128;
#pragma unroll
        for (int i = 0; i < 4; i++) {
#pragma unroll
            for (int jp = 0; jp < 4; jp++) {
                float2 f = unpack2(accp[i][jp]);
                float sv[2] = {f.x, f.y};
#pragma unroll
                for (int h = 0; h < 2; h++) {
                    int u = ub + tx*8 + 2*jp + h;
                    float s = (u < cvr[i]) ? sv[h] : NEGV;
                    if (s > b1[i] || (s == b1[i] && u < i1[i])) {
                        b2[i] = b1[i]; i2[i] = i1[i]; b1[i] = s; i1[i] = u;
                    } else if (s > b2[i] || (s == b2[i] && u < i2[i])) {
                        b2[i] = s; i2[i] = u;
                    }
                }
            }
        }
    }

    // reduce across the 16 tx lanes
#pragma unroll
    for (int off = 1; off < 16; off <<= 1) {
#pragma unroll
        for (int i = 0; i < 4; i++) {
            float ob1 = __shfl_xor_sync(0xffffffffu, b1[i], off);
            int   oi1 = __shfl_xor_sync(0xffffffffu, i1[i], off);
            float ob2 = __shfl_xor_sync(0xffffffffu, b2[i], off);
            int   oi2 = __shfl_xor_sync(0xffffffffu, i2[i], off);
            if (ob1 > b1[i] || (ob1 == b1[i] && oi1 < i1[i])) {
                float n2; int n2i;
                if (b1[i] > ob2 || (b1[i] == ob2 && i1[i] < oi2)) { n2 = b1[i]; n2i = i1[i]; }
                else { n2 = ob2; n2i = oi2; }
                b1[i] = ob1; i1[i] = oi1; b2[i] = n2; i2[i] = n2i;
            } else if (ob1 > b2[i] || (ob1 == b2[i] && oi1 < i2[i])) {
                b2[i] = ob1; i2[i] = oi1;
            }
        }
    }
    if (tx == 0) {
#pragma unroll
        for (int i = 0; i < 4; i++) {
            int v = v0 + ty*4 + i;
            int o = (v*NSLAB + slab)*2;
            g_pval[o]   = b1[i]; g_pidx[o]   = i1[i];
            g_pval[o+1] = b2[i]; g_pidx[o+1] = i2[i];
        }
    }
}

// ---------------- fused merge + inversion-bit MLP + valid flags ----------------
__global__ void k_mergefinal(const float* __restrict__ w2, const float* __restrict__ b2,
                             const float* __restrict__ x, const int* __restrict__ depth,
                             float* __restrict__ out)
{
    int v = blockIdx.x;
    int j = threadIdx.x;            // 128 threads
    __shared__ int su[2];
    __shared__ float wsum[2][4];

    if (j == 0) {
        float a1 = -INFINITY, a2 = -INFINITY; int ai1 = 0x7fffffff, ai2 = 0x7fffffff;
#pragma unroll
        for (int s = 0; s < NSLAB; s++) {
            int o = (v*NSLAB + s)*2;
            float c1 = g_pval[o]; int ci1 = g_pidx[o];
            float c2 = g_pval[o+1]; int ci2 = g_pidx[o+1];
            if (c1 > a1 || (c1 == a1 && ci1 < ai1)) {
                float n2; int n2i;
                if (a1 > c2 || (a1 == c2 && ai1 < ci2)) { n2 = a1; n2i = ai1; }
                else { n2 = c2; n2i = ci2; }
                a1 = c1; ai1 = ci1; a2 = n2; ai2 = n2i;
            } else if (c1 > a2 || (c1 == a2 && ci1 < ai2)) {
                a2 = c1; ai2 = ci1;
            }
        }
        out[v*2 + 0] = a1;
        out[v*2 + 1] = a2;
        out[4*Nn + v*2 + 0] = (float)ai1;
        out[4*Nn + v*2 + 1] = (float)ai2;
        su[0] = (ai1 >= 0 && ai1 < Nn) ? ai1 : 0;
        su[1] = (ai2 >= 0 && ai2 < Nn) ? ai2 : 0;
    }
    __syncthreads();

#pragma unroll
    for (int k = 0; k < 2; k++) {
        int u = su[k];
        float t = g_P[u*Hh + j] + g_Q[v*Hh + j] + g_czb[j];
        t = fmaxf(t, 0.0f);
        float p = t * w2[j];
#pragma unroll
        for (int off = 16; off > 0; off >>= 1)
            p += __shfl_xor_sync(0xffffffffu, p, off);
        if ((j & 31) == 0) wsum[k][j >> 5] = p;
    }
    __syncthreads();
    if (j < 2) {
        float lg = wsum[j][0] + wsum[j][1] + wsum[j][2] + wsum[j][3] + b2[0];
        out[2*Nn + v*2 + j] = lg;
        out[6*Nn + v*2 + j] = (lg > 0.0f) ? 1.0f : 0.0f;
    } else if (j == 2) {
        int tpy = (int)x[v*2];
        int c = g_cv[v];
        bool tv = (depth[v] >= 1) && (tpy != 0);
        out[8*Nn + v*2 + 0] = (tv && c >= 1) ? 1.0f : 0.0f;
        out[8*Nn + v*2 + 1] = (tv && tpy == 2 && c >= 2) ? 1.0f : 0.0f;
    }
}

// ---------------- launch ----------------
extern "C" void kernel_launch(void* const* d_in, const int* in_sizes, int n_in,
                              void* d_out, int out_size)
{
    const float* x     = (const float*)d_in[0];
    const float* z     = (const float*)d_in[1];
    const int*   ei    = (const int*)  d_in[2];
    const int*   depth = (const int*)  d_in[3];
    const float* c1w = (const float*)d_in[4];
    const float* c1b = (const float*)d_in[5];
    const float* c2w = (const float*)d_in[6];
    const float* c2b = (const float*)d_in[7];
    const float* np1w = (const float*)d_in[8];
    const float* np1b = (const float*)d_in[9];
    const float* np2w = (const float*)d_in[10];
    const float* np2b = (const float*)d_in[11];
    const float* srcw = (const float*)d_in[12];
    const float* tgtw = (const float*)d_in[13];
    const float* i1w  = (const float*)d_in[14];
    const float* i1b  = (const float*)d_in[15];
    const float* i2w  = (const float*)d_in[16];
    const float* i2b  = (const float*)d_in[17];
    const int* esrc = ei;
    const int* edst = ei + Ee;
    float* out = (float*)d_out;

    cudaFuncSetAttribute(k_gemm,  cudaFuncAttributeMaxDynamicSharedMemorySize, SMEM_BYTES);
    cudaFuncSetAttribute(k_proj,  cudaFuncAttributeMaxDynamicSharedMemorySize, SMEM_BYTES);
    cudaFuncSetAttribute(k_score, cudaFuncAttributeMaxDynamicSharedMemorySize, SMEM_BYTES);

    const int NB = 256;
    k_deg_init <<<Nn/NB, NB>>>();
    k_deg_count<<<Ee/NB, NB>>>(edst);
    k_rsq      <<<Nn/NB, NB>>>();
    // GCN layer 1 (xw + zero agg fused)
    k_xw1      <<<(Nn*Hh)/NB, NB>>>(x, c1w);
    k_edge_agg <<<(Ee*32)/NB, NB>>>(esrc, edst);
    k_post     <<<(Nn*Hh)/NB, NB>>>(c1b);
    // GCN layer 2 (gemm epilogue zeroes g_agg)
    k_gemm<<<Nn/64, NB, SMEM_BYTES>>>(SEL_H, c2w, 128, nullptr, 0, SEL_XW, 0, 1);
    k_edge_agg <<<(Ee*32)/NB, NB>>>(esrc, edst);
    k_post     <<<(Nn*Hh)/NB, NB>>>(c2b);
    // z-dependent constant vectors
    k_zvec<<<1, 256>>>(np1w, np1b, i1w, i1b, z);
    // node_proj
    k_gemm<<<Nn/64, NB, SMEM_BYTES>>>(SEL_H, np1w, 256, nullptr, 1, SEL_T, 1, 0);
    k_gemm<<<Nn/64, NB, SMEM_BYTES>>>(SEL_T, np2w, 128, np2b,    0, SEL_H, 0, 0);
    // fused projections (Ht, Hs, P, Q)
    dim3 pgrid(Nn/64, 4);
    k_proj<<<pgrid, NB, SMEM_BYTES>>>(tgtw, srcw, i1w);
    // candidate counts (+ partial init) and fused score/top-2
    k_cv<<<Nn/NB, NB>>>(depth);
    dim3 sgrid(NSLAB, Nn/64);
    k_score<<<sgrid, NB, SMEM_BYTES>>>();
    // merge + inv-MLP + valid
    k_mergefinal<<<Nn, 128>>>(i2w, i2b, x, depth, out);
    (void)in_sizes; (void)n_in; (void)out_size;
}

// round 6
// speedup vs baseline: 1.2183x; 1.2183x over previous
#include <cuda_runtime.h>
#include <math.h>
#include <stdint.h>

#define Nn 8192
#define Ee 131072
#define Hh 128
#define NEGV (-1e30f)
#define NSLAB 16
#define PAD 132
#define SMEM_GEMM  (2*128*PAD*4)     // 135 KB: As + Bs
#define SMEM_SCORE (3*128*PAD*4)     // 203 KB: As + 2x Bs (double buffer)

// ---------------- device scratch (no allocations allowed) ----------------
__device__ __align__(16) float g_deg[Nn];
__device__ __align__(16) float g_rsq[Nn];
__device__ __align__(16) float g_xw[Nn*Hh];
__device__ __align__(16) float g_agg[Nn*Hh];
__device__ __align__(16) float g_h[Nn*Hh];
__device__ __align__(16) float g_t[Nn*Hh];
__device__ __align__(16) float g_Ht[Nn*Hh];
__device__ __align__(16) float g_Hs[Nn*Hh];
__device__ __align__(16) float g_P[Nn*Hh];
__device__ __align__(16) float g_Q[Nn*Hh];
__device__ __align__(16) float g_vz[Hh];
__device__ __align__(16) float g_czb[Hh];
__device__ int   g_cv[Nn];
__device__ __align__(16) float g_pval[Nn*NSLAB*2];
__device__ int   g_pidx[Nn*NSLAB*2];

#define SEL_H  0
#define SEL_XW 1
#define SEL_T  2
__device__ __forceinline__ float* buf_ptr(int sel) {
    switch (sel) {
        case SEL_H:  return g_h;
        case SEL_XW: return g_xw;
        default:     return g_t;
    }
}

// ---------------- packed f32x2 helpers ----------------
__device__ __forceinline__ unsigned long long pack2(float x, float y) {
    unsigned long long r;
    asm("mov.b64 %0, {%1, %2};" : "=l"(r) : "f"(x), "f"(y));
    return r;
}
__device__ __forceinline__ float2 unpack2(unsigned long long v) {
    float2 r;
    asm("mov.b64 {%0, %1}, %2;" : "=f"(r.x), "=f"(r.y) : "l"(v));
    return r;
}
__device__ __forceinline__ void fma2(unsigned long long &acc, unsigned long long a2, unsigned long long b2) {
    asm("fma.rn.f32x2 %0, %1, %2, %0;" : "+l"(acc) : "l"(a2), "l"(b2));
}
__device__ __forceinline__ void red4(float* p, float a, float b, float c, float d) {
    asm volatile("red.global.add.v4.f32 [%0], {%1,%2,%3,%4};"
                 :: "l"(p), "f"(a), "f"(b), "f"(c), "f"(d) : "memory");
}

// Conflict-free k-major transpose load: G rows [row0,row0+128) x 128 cols (stride ld) -> S[k][r]
__device__ __forceinline__ void load_tile_T(const float* __restrict__ G, int row0, int ld,
                                            float* S, int tid) {
#pragma unroll
    for (int i = 0; i < 16; i++) {
        int r  = (tid & 31) + 32*(i >> 2);
        int kq = (tid >> 5) + 8*(i & 3);
        float4 v = *(const float4*)(G + (row0 + r)*ld + kq*4);
        S[(kq*4+0)*PAD + r] = v.x;
        S[(kq*4+1)*PAD + r] = v.y;
        S[(kq*4+2)*PAD + r] = v.z;
        S[(kq*4+3)*PAD + r] = v.w;
    }
}

// 8x8 microtile inner product over K=128, packed f32x2 accumulators [8 rows][4 col-pairs]
__device__ __forceinline__ void mm_inner(const float* As, const float* Bs, int ty, int tx,
                                         unsigned long long accp[8][4]) {
#pragma unroll 4
    for (int k = 0; k < 128; k++) {
        const float4 a0 = *(const float4*)&As[k*PAD + ty*8];
        const float4 a1 = *(const float4*)&As[k*PAD + ty*8 + 4];
        const float4 b0 = *(const float4*)&Bs[k*PAD + tx*8];
        const float4 b1 = *(const float4*)&Bs[k*PAD + tx*8 + 4];
        unsigned long long bp[4];
        bp[0] = pack2(b0.x, b0.y); bp[1] = pack2(b0.z, b0.w);
        bp[2] = pack2(b1.x, b1.y); bp[3] = pack2(b1.z, b1.w);
        float av[8] = {a0.x, a0.y, a0.z, a0.w, a1.x, a1.y, a1.z, a1.w};
#pragma unroll
        for (int i = 0; i < 8; i++) {
            unsigned long long ap = pack2(av[i], av[i]);
            fma2(accp[i][0], ap, bp[0]);
            fma2(accp[i][1], ap, bp[1]);
            fma2(accp[i][2], ap, bp[2]);
            fma2(accp[i][3], ap, bp[3]);
        }
    }
}

// ---------------- small kernels ----------------
__global__ void k_deg_init() {
    int i = blockIdx.x*blockDim.x + threadIdx.x;
    if (i < Nn) g_deg[i] = 1.0f;
}
__global__ void k_deg_count(const int* __restrict__ dst) {
    int e = blockIdx.x*blockDim.x + threadIdx.x;
    if (e < Ee) atomicAdd(&g_deg[dst[e]], 1.0f);
}
__global__ void k_rsq() {
    int i = blockIdx.x*blockDim.x + threadIdx.x;
    if (i < Nn) g_rsq[i] = rsqrtf(g_deg[i]);
}
__global__ void k_xw1(const float* __restrict__ x, const float* __restrict__ w) {
    int idx = blockIdx.x*blockDim.x + threadIdx.x;
    if (idx >= Nn*Hh) return;
    int i = idx >> 7, j = idx & 127;
    g_xw[idx] = fmaf(x[2*i], w[2*j], x[2*i+1]*w[2*j+1]);
    g_agg[idx] = 0.0f;
}
__global__ void k_edge_agg(const int* __restrict__ src, const int* __restrict__ dst) {
    int idx = blockIdx.x*blockDim.x + threadIdx.x;
    if (idx >= Ee*32) return;
    int e = idx >> 5, q = idx & 31;
    int s = src[e], d = dst[e];
    float sc = g_rsq[s]*g_rsq[d];
    const float4 v = *(const float4*)(g_xw + s*Hh + q*4);
    red4(g_agg + d*Hh + q*4, sc*v.x, sc*v.y, sc*v.z, sc*v.w);
}
__global__ void k_post(const float* __restrict__ b) {
    int idx = blockIdx.x*blockDim.x + threadIdx.x;
    if (idx >= Nn*Hh) return;
    int i = idx >> 7, j = idx & 127;
    float v = g_agg[idx] + g_xw[idx]/g_deg[i] + b[j];
    g_h[idx] = fmaxf(v, 0.0f);
}
__global__ void k_zvec(const float* __restrict__ np1w, const float* __restrict__ np1b,
                       const float* __restrict__ i1w, const float* __restrict__ i1b,
                       const float* __restrict__ z) {
    int t = threadIdx.x;
    if (t < 128) {
        float s = np1b[t];
        for (int k = 0; k < 128; k++) s = fmaf(np1w[t*256 + 128 + k], z[k], s);
        g_vz[t] = s;
    } else if (t < 256) {
        int j = t - 128;
        float s = i1b[j];
        for (int k = 0; k < 128; k++) s = fmaf(i1w[j*384 + 256 + k], z[k], s);
        g_czb[j] = s;
    }
}
// candidate counts + partial-top2 init (fused)
__global__ void k_cv(const int* __restrict__ depth) {
    int v = blockIdx.x*blockDim.x + threadIdx.x;
    if (v >= Nn) return;
    int thr = depth[v] + 1;
    int lo = 0, hi = Nn;
    while (lo < hi) { int mid = (lo + hi) >> 1; if (depth[mid] <= thr) lo = mid + 1; else hi = mid; }
    g_cv[v] = lo;
#pragma unroll
    for (int s = 0; s < NSLAB*2; s++) {
        g_pval[v*NSLAB*2 + s] = -INFINITY;
        g_pidx[v*NSLAB*2 + s] = 0x7fffffff;
    }
}

// ---------------- fp32 GEMM: C[8192 x 128] = A @ W^T (+bias, relu) ----------------
__global__ void __launch_bounds__(256) k_gemm(
    int a_sel, const float* __restrict__ W, int ldw,
    const float* __restrict__ bias, int bias_vz, int c_sel, int relu, int zero_agg)
{
    extern __shared__ float sm[];
    float* As = sm;
    float* Bs = sm + 128*PAD;
    const float* A = buf_ptr(a_sel);
    float* C = buf_ptr(c_sel);
    const float* bptr = bias_vz ? g_vz : bias;
    int tid = threadIdx.x;
    int r0 = blockIdx.x * 128;

    load_tile_T(A, r0, 128, As, tid);
    load_tile_T(W, 0, ldw, Bs, tid);
    __syncthreads();

    int ty = tid >> 4, tx = tid & 15;
    unsigned long long accp[8][4];
#pragma unroll
    for (int i = 0; i < 8; i++)
#pragma unroll
        for (int j = 0; j < 4; j++) accp[i][j] = 0ull;
    mm_inner(As, Bs, ty, tx, accp);

#pragma unroll
    for (int i = 0; i < 8; i++) {
        int r = r0 + ty*8 + i;
        float o[8];
#pragma unroll
        for (int jp = 0; jp < 4; jp++) {
            float2 f = unpack2(accp[i][jp]);
            o[2*jp] = f.x; o[2*jp+1] = f.y;
        }
#pragma unroll
        for (int j = 0; j < 8; j++) {
            if (bptr) o[j] += bptr[tx*8 + j];
            if (relu) o[j] = fmaxf(o[j], 0.0f);
        }
        *(float4*)(C + r*128 + tx*8)     = make_float4(o[0], o[1], o[2], o[3]);
        *(float4*)(C + r*128 + tx*8 + 4) = make_float4(o[4], o[5], o[6], o[7]);
        if (zero_agg) {
            *(float4*)(g_agg + r*128 + tx*8)     = make_float4(0.f, 0.f, 0.f, 0.f);
            *(float4*)(g_agg + r*128 + tx*8 + 4) = make_float4(0.f, 0.f, 0.f, 0.f);
        }
    }
}

// fused 4-way projection: blockIdx.y selects (W, ld, C): Ht, Hs, P, Q
__global__ void __launch_bounds__(256) k_proj(
    const float* __restrict__ tgtw, const float* __restrict__ srcw,
    const float* __restrict__ i1w)
{
    extern __shared__ float sm[];
    float* As = sm;
    float* Bs = sm + 128*PAD;
    const float* W; int ldw; float* C;
    switch (blockIdx.y) {
        case 0: W = tgtw;       ldw = 128; C = g_Ht; break;
        case 1: W = srcw;       ldw = 128; C = g_Hs; break;
        case 2: W = i1w;        ldw = 384; C = g_P;  break;
        default: W = i1w + 128; ldw = 384; C = g_Q;  break;
    }
    int tid = threadIdx.x;
    int r0 = blockIdx.x * 128;

    load_tile_T(g_h, r0, 128, As, tid);
    load_tile_T(W, 0, ldw, Bs, tid);
    __syncthreads();

    int ty = tid >> 4, tx = tid & 15;
    unsigned long long accp[8][4];
#pragma unroll
    for (int i = 0; i < 8; i++)
#pragma unroll
        for (int j = 0; j < 4; j++) accp[i][j] = 0ull;
    mm_inner(As, Bs, ty, tx, accp);

#pragma unroll
    for (int i = 0; i < 8; i++) {
        int r = r0 + ty*8 + i;
#pragma unroll
        for (int jp = 0; jp < 2; jp++) {
            float2 f0 = unpack2(accp[i][2*jp]);
            float2 f1 = unpack2(accp[i][2*jp+1]);
            *(float4*)(C + r*128 + tx*8 + 4*jp) = make_float4(f0.x, f0.y, f1.x, f1.y);
        }
    }
}

// ---------------- fused score GEMM + masked top-2 (double-buffered Bs) ----------------
// grid (NSLAB, Nn/128). slab s handles chunks c ≡ s (mod NSLAB); chunk c = u in [c*128, c*128+128).
__global__ void __launch_bounds__(256) k_score()
{
    extern __shared__ float sm[];
    float* As = sm;
    float* Bsb[2] = { sm + 128*PAD, sm + 2*128*PAD };
    int v0 = blockIdx.y * 128;
    int slab = blockIdx.x;

    int cmax = g_cv[v0 + 127];          // c_v non-decreasing (depth sorted)
    int uend = cmax < 2 ? 2 : cmax;     // >=2 so masked NEG idx ties match top_k
    if (uend > Nn) uend = Nn;
    int nchunk = (uend + 127) >> 7;
    if (slab >= nchunk) return;

    int tid = threadIdx.x;
    load_tile_T(g_Ht, v0, 128, As, tid);

    int ty = tid >> 4, tx = tid & 15;
    int cvr[8]; float b1[8], b2[8]; int i1[8], i2[8];
#pragma unroll
    for (int i = 0; i < 8; i++) {
        cvr[i] = g_cv[v0 + ty*8 + i];
        b1[i] = -INFINITY; b2[i] = -INFINITY; i1[i] = 0x7fffffff; i2[i] = 0x7fffffff;
    }

    // per-thread lane mapping (matches load_tile_T)
    int pr[16], pk[16];
#pragma unroll
    for (int i = 0; i < 16; i++) {
        pr[i] = (tid & 31) + 32*(i >> 2);
        pk[i] = (tid >> 5) + 8*(i & 3);
    }

    // prologue: fetch chunk 'slab' into buf 0
    float4 pf[16];
    int c = slab;
#pragma unroll
    for (int i = 0; i < 16; i++)
        pf[i] = *(const float4*)(g_Hs + (c*128 + pr[i])*128 + pk[i]*4);
    {
        float* B = Bsb[0];
#pragma unroll
        for (int i = 0; i < 16; i++) {
            B[(pk[i]*4+0)*PAD + pr[i]] = pf[i].x;
            B[(pk[i]*4+1)*PAD + pr[i]] = pf[i].y;
            B[(pk[i]*4+2)*PAD + pr[i]] = pf[i].z;
            B[(pk[i]*4+3)*PAD + pr[i]] = pf[i].w;
        }
    }
    __syncthreads();

    int buf = 0;
    while (c < nchunk) {
        int cn = c + NSLAB;
        if (cn < nchunk) {
#pragma unroll
            for (int i = 0; i < 16; i++)
                pf[i] = *(const float4*)(g_Hs + (cn*128 + pr[i])*128 + pk[i]*4);
        }

        unsigned long long accp[8][4];
#pragma unroll
        for (int i = 0; i < 8; i++)
#pragma unroll
            for (int j = 0; j < 4; j++) accp[i][j] = 0ull;
        mm_inner(As, Bsb[buf], ty, tx, accp);

        if (cn < nchunk) {
            float* B = Bsb[buf^1];
#pragma unroll
            for (int i = 0; i < 16; i++) {
                B[(pk[i]*4+0)*PAD + pr[i]] = pf[i].x;
                B[(pk[i]*4+1)*PAD + pr[i]] = pf[i].y;
                B[(pk[i]*4+2)*PAD + pr[i]] = pf[i].z;
                B[(pk[i]*4+3)*PAD + pr[i]] = pf[i].w;
            }
        }

        // top-2 update for this chunk (tie: lower index wins, matching lax.top_k)
        int ub = c*128;
#pragma unroll
        for (int i = 0; i < 8; i++) {
#pragma unroll
            for (int jp = 0; jp < 4; jp++) {
                float2 f = unpack2(accp[i][jp]);
                float sv[2] = {f.x, f.y};
#pragma unroll
                for (int h = 0; h < 2; h++) {
                    int u = ub + tx*8 + 2*jp + h;
                    float s = (u < cvr[i]) ? sv[h] : NEGV;
                    if (s > b1[i] || (s == b1[i] && u < i1[i])) {
                        b2[i] = b1[i]; i2[i] = i1[i]; b1[i] = s; i1[i] = u;
                    } else if (s > b2[i] || (s == b2[i] && u < i2[i])) {
                        b2[i] = s; i2[i] = u;
                    }
                }
            }
        }
        __syncthreads();
        buf ^= 1;
        c = cn;
    }

    // reduce across the 16 tx lanes
#pragma unroll
    for (int off = 1; off < 16; off <<= 1) {
#pragma unroll
        for (int i = 0; i < 8; i++) {
            float ob1 = __shfl_xor_sync(0xffffffffu, b1[i], off);
            int   oi1 = __shfl_xor_sync(0xffffffffu, i1[i], off);
            float ob2 = __shfl_xor_sync(0xffffffffu, b2[i], off);
            int   oi2 = __shfl_xor_sync(0xffffffffu, i2[i], off);
            if (ob1 > b1[i] || (ob1 == b1[i] && oi1 < i1[i])) {
                float n2; int n2i;
                if (b1[i] > ob2 || (b1[i] == ob2 && i1[i] < oi2)) { n2 = b1[i]; n2i = i1[i]; }
                else { n2 = ob2; n2i = oi2; }
                b1[i] = ob1; i1[i] = oi1; b2[i] = n2; i2[i] = n2i;
            } else if (ob1 > b2[i] || (ob1 == b2[i] && oi1 < i2[i])) {
                b2[i] = ob1; i2[i] = oi1;
            }
        }
    }
    if (tx == 0) {
#pragma unroll
        for (int i = 0; i < 8; i++) {
            int v = v0 + ty*8 + i;
            int o = (v*NSLAB + slab)*2;
            g_pval[o]   = b1[i]; g_pidx[o]   = i1[i];
            g_pval[o+1] = b2[i]; g_pidx[o+1] = i2[i];
        }
    }
}

// ---------------- fused merge + inversion-bit MLP + valid flags ----------------
__global__ void k_mergefinal(const float* __restrict__ w2, const float* __restrict__ b2,
                             const float* __restrict__ x, const int* __restrict__ depth,
                             float* __restrict__ out)
{
    int v = blockIdx.x;
    int j = threadIdx.x;            // 128 threads
    __shared__ int su[2];
    __shared__ float wsum[2][4];

    if (j == 0) {
        float a1 = -INFINITY, a2 = -INFINITY; int ai1 = 0x7fffffff, ai2 = 0x7fffffff;
#pragma unroll
        for (int s = 0; s < NSLAB; s++) {
            int o = (v*NSLAB + s)*2;
            float c1 = g_pval[o]; int ci1 = g_pidx[o];
            float c2 = g_pval[o+1]; int ci2 = g_pidx[o+1];
            if (c1 > a1 || (c1 == a1 && ci1 < ai1)) {
                float n2; int n2i;
                if (a1 > c2 || (a1 == c2 && ai1 < ci2)) { n2 = a1; n2i = ai1; }
                else { n2 = c2; n2i = ci2; }
                a1 = c1; ai1 = ci1; a2 = n2; ai2 = n2i;
            } else if (c1 > a2 || (c1 == a2 && ci1 < ai2)) {
                a2 = c1; ai2 = ci1;
            }
        }
        out[v*2 + 0] = a1;
        out[v*2 + 1] = a2;
        out[4*Nn + v*2 + 0] = (float)ai1;
        out[4*Nn + v*2 + 1] = (float)ai2;
        su[0] = (ai1 >= 0 && ai1 < Nn) ? ai1 : 0;
        su[1] = (ai2 >= 0 && ai2 < Nn) ? ai2 : 0;
    }
    __syncthreads();

#pragma unroll
    for (int k = 0; k < 2; k++) {
        int u = su[k];
        float t = g_P[u*Hh + j] + g_Q[v*Hh + j] + g_czb[j];
        t = fmaxf(t, 0.0f);
        float p = t * w2[j];
#pragma unroll
        for (int off = 16; off > 0; off >>= 1)
            p += __shfl_xor_sync(0xffffffffu, p, off);
        if ((j & 31) == 0) wsum[k][j >> 5] = p;
    }
    __syncthreads();
    if (j < 2) {
        float lg = wsum[j][0] + wsum[j][1] + wsum[j][2] + wsum[j][3] + b2[0];
        out[2*Nn + v*2 + j] = lg;
        out[6*Nn + v*2 + j] = (lg > 0.0f) ? 1.0f : 0.0f;
    } else if (j == 2) {
        int tpy = (int)x[v*2];
        int c = g_cv[v];
        bool tv = (depth[v] >= 1) && (tpy != 0);
        out[8*Nn + v*2 + 0] = (tv && c >= 1) ? 1.0f : 0.0f;
        out[8*Nn + v*2 + 1] = (tv && tpy == 2 && c >= 2) ? 1.0f : 0.0f;
    }
}

// ---------------- launch ----------------
extern "C" void kernel_launch(void* const* d_in, const int* in_sizes, int n_in,
                              void* d_out, int out_size)
{
    const float* x     = (const float*)d_in[0];
    const float* z     = (const float*)d_in[1];
    const int*   ei    = (const int*)  d_in[2];
    const int*   depth = (const int*)  d_in[3];
    const float* c1w = (const float*)d_in[4];
    const float* c1b = (const float*)d_in[5];
    const float* c2w = (const float*)d_in[6];
    const float* c2b = (const float*)d_in[7];
    const float* np1w = (const float*)d_in[8];
    const float* np1b = (const float*)d_in[9];
    const float* np2w = (const float*)d_in[10];
    const float* np2b = (const float*)d_in[11];
    const float* srcw = (const float*)d_in[12];
    const float* tgtw = (const float*)d_in[13];
    const float* i1w  = (const float*)d_in[14];
    const float* i1b  = (const float*)d_in[15];
    const float* i2w  = (const float*)d_in[16];
    const float* i2b  = (const float*)d_in[17];
    const int* esrc = ei;
    const int* edst = ei + Ee;
    float* out = (float*)d_out;

    cudaFuncSetAttribute(k_gemm,  cudaFuncAttributeMaxDynamicSharedMemorySize, SMEM_GEMM);
    cudaFuncSetAttribute(k_proj,  cudaFuncAttributeMaxDynamicSharedMemorySize, SMEM_GEMM);
    cudaFuncSetAttribute(k_score, cudaFuncAttributeMaxDynamicSharedMemorySize, SMEM_SCORE);

    const int NB = 256;
    k_deg_init <<<Nn/NB, NB>>>();
    k_deg_count<<<Ee/NB, NB>>>(edst);
    k_rsq      <<<Nn/NB, NB>>>();
    // GCN layer 1 (xw + zero agg fused)
    k_xw1      <<<(Nn*Hh)/NB, NB>>>(x, c1w);
    k_edge_agg <<<(Ee*32)/NB, NB>>>(esrc, edst);
    k_post     <<<(Nn*Hh)/NB, NB>>>(c1b);
    // GCN layer 2 (gemm epilogue zeroes g_agg)
    k_gemm<<<Nn/128, NB, SMEM_GEMM>>>(SEL_H, c2w, 128, nullptr, 0, SEL_XW, 0, 1);
    k_edge_agg <<<(Ee*32)/NB, NB>>>(esrc, edst);
    k_post     <<<(Nn*Hh)/NB, NB>>>(c2b);
    // z-dependent constant vectors
    k_zvec<<<1, 256>>>(np1w, np1b, i1w, i1b, z);
    // node_proj
    k_gemm<<<Nn/128, NB, SMEM_GEMM>>>(SEL_H, np1w, 256, nullptr, 1, SEL_T, 1, 0);
    k_gemm<<<Nn/128, NB, SMEM_GEMM>>>(SEL_T, np2w, 128, np2b,    0, SEL_H, 0, 0);
    // fused projections (Ht, Hs, P, Q)
    dim3 pgrid(Nn/128, 4);
    k_proj<<<pgrid, NB, SMEM_GEMM>>>(tgtw, srcw, i1w);
    // candidate counts (+ partial init) and fused score/top-2
    k_cv<<<Nn/NB, NB>>>(depth);
    dim3 sgrid(NSLAB, Nn/128);
    k_score<<<sgrid, NB, SMEM_SCORE>>>();
    // merge + inv-MLP + valid
    k_mergefinal<<<Nn, 128>>>(i2w, i2b, x, depth, out);
    (void)in_sizes; (void)n_in; (void)out_size;
}